// round 16
// baseline (speedup 1.0000x reference)
#include <cuda_runtime.h>
#include <cuda_fp16.h>
#include <math.h>
#include <stdint.h>

// ---------------- problem constants ----------------
#define BSZ    4
#define TSEQ   2048
#define DMODEL 1024
#define NH     16
#define DK     64
#define MROWS  (BSZ*TSEQ)          // 8192
#define QKV_ELEMS (BSZ*NH*TSEQ*DK) // 8388608

// ---------------- scratch (static device globals) ----------------
__device__ __half g_A16[MROWS*DMODEL];       // x quantized fp16 (QKV GEMM A)
__device__ __half g_O16[MROWS*DMODEL];       // attention output fp16 (out GEMM A)
__device__ __half g_Q16[QKV_ELEMS];          // Q fp16 single (pre-scaled)
__device__ __half g_K16[QKV_ELEMS];          // K fp16 single
__device__ __half g_V16[QKV_ELEMS];          // V fp16 single
__device__ __half g_Wq16[DMODEL*DMODEL], g_Wk16[DMODEL*DMODEL];
__device__ __half g_Wv16[DMODEL*DMODEL], g_Wo16[DMODEL*DMODEL];
__device__ float2 g_rope[TSEQ*32];           // (cos, sin) per (t, pair)

// =========================================================================
// PTX helpers
// =========================================================================
__device__ __forceinline__ uint32_t smem_u32(const void* p) {
    uint32_t a;
    asm("{ .reg .u64 t; cvta.to.shared.u64 t, %1; cvt.u32.u64 %0, t; }"
        : "=r"(a) : "l"(p));
    return a;
}
#define SW128(off) ((off) ^ (((off) >> 3) & 0x70))

__device__ __forceinline__ void cp_async16(uint32_t s, const void* g) {
    asm volatile("cp.async.cg.shared.global [%0], [%1], 16;" :: "r"(s), "l"(g));
}
__device__ __forceinline__ void cp_commit() {
    asm volatile("cp.async.commit_group;" ::: "memory");
}
template <int N> __device__ __forceinline__ void cp_wait() {
    asm volatile("cp.async.wait_group %0;" :: "n"(N) : "memory");
}

__device__ __forceinline__ void ldm_x4(uint32_t* r, uint32_t addr) {
    asm volatile("ldmatrix.sync.aligned.m8n8.x4.shared.b16 {%0,%1,%2,%3}, [%4];"
        : "=r"(r[0]), "=r"(r[1]), "=r"(r[2]), "=r"(r[3]) : "r"(addr));
}
__device__ __forceinline__ void ldm_x4_t(uint32_t* r, uint32_t addr) {
    asm volatile("ldmatrix.sync.aligned.m8n8.x4.trans.shared.b16 {%0,%1,%2,%3}, [%4];"
        : "=r"(r[0]), "=r"(r[1]), "=r"(r[2]), "=r"(r[3]) : "r"(addr));
}

__device__ __forceinline__ void mma16816h(float* c, const uint32_t* a,
                                          uint32_t b0, uint32_t b1) {
    asm volatile(
        "mma.sync.aligned.m16n8k16.row.col.f32.f16.f16.f32 "
        "{%0,%1,%2,%3}, {%4,%5,%6,%7}, {%8,%9}, {%0,%1,%2,%3};"
        : "+f"(c[0]), "+f"(c[1]), "+f"(c[2]), "+f"(c[3])
        : "r"(a[0]), "r"(a[1]), "r"(a[2]), "r"(a[3]), "r"(b0), "r"(b1));
}

__device__ __forceinline__ uint32_t packh2(__half a, __half b) {
    __half2 t = __halves2half2(a, b);
    return *reinterpret_cast<uint32_t*>(&t);
}

// =========================================================================
// fp32 -> single fp16 quantize
// =========================================================================
__global__ void quant_kernel(const float* __restrict__ src,
                             __half* __restrict__ dst, int n)
{
    int i = (blockIdx.x * blockDim.x + threadIdx.x) * 4;
    if (i >= n) return;
    float4 v = *(const float4*)(src + i);
    *(__half2*)(dst + i)     = __halves2half2(__float2half(v.x), __float2half(v.y));
    *(__half2*)(dst + i + 2) = __halves2half2(__float2half(v.z), __float2half(v.w));
}

// 4 weights -> single fp16, one launch
__global__ void quant_w4(const float* __restrict__ w0, const float* __restrict__ w1,
                         const float* __restrict__ w2, const float* __restrict__ w3,
                         int n)
{
    const float* src;
    __half* dst;
    switch (blockIdx.z) {
        case 0: src = w0; dst = g_Wq16; break;
        case 1: src = w1; dst = g_Wk16; break;
        case 2: src = w2; dst = g_Wv16; break;
        default: src = w3; dst = g_Wo16; break;
    }
    int i = (blockIdx.x * blockDim.x + threadIdx.x) * 4;
    if (i >= n) return;
    float4 v = *(const float4*)(src + i);
    *(__half2*)(dst + i)     = __halves2half2(__float2half(v.x), __float2half(v.y));
    *(__half2*)(dst + i + 2) = __halves2half2(__float2half(v.z), __float2half(v.w));
}

// rope cos/sin table
__global__ void rope_table_kernel()
{
    int idx = blockIdx.x * blockDim.x + threadIdx.x;   // 65536
    int c = idx & 31, t = idx >> 5;
    float invf = exp2f(-(float)c * (0.03125f * 13.287712379549449f));
    float s, cs;
    sincosf((float)t * invf, &s, &cs);
    g_rope[idx] = make_float2(cs, s);
}

// =========================================================================
// pure fp16 GEMM core: C = A16 * B16^T + bias.
// CTA 128m x 256n, K-chunk 64, TRIPLE buffered cp.async.
// 512 threads, 16 warps in 4(m) x 4(n), warp tile 32x64.
// Inner loop: register double-buffered ldmatrix fragments (prefetch ks+1
// while issuing ks MMAs) to cover LDS latency.
// =========================================================================
#define KCH 64
#define NKB (DMODEL / KCH)        // 16
#define A_TILE 16384              // 128 rows * 128B
#define B_TILE 32768              // 256 rows * 128B
#define STG_SZ (A_TILE + B_TILE)      // 49152
#define GEMM_SMEM (3 * STG_SZ)        // 147456
#define GT 512

__device__ __forceinline__ void gemm_core(
    const __half* __restrict__ A16, const __half* __restrict__ B16,
    const float* __restrict__ bias, float* __restrict__ out,
    __half* __restrict__ outh,
    int mode, float scale, char* smem, int m0, int n0)
{
    uint32_t sb = smem_u32(smem);
    int tid = threadIdx.x, lane = tid & 31, wid = tid >> 5;   // 0..15
    int wm = wid & 3, wn = wid >> 2;      // 4(m) x 4(n), warp tile 32x64

    float acc[2][8][4];
#pragma unroll
    for (int i = 0; i < 2; i++)
#pragma unroll
        for (int j = 0; j < 8; j++)
#pragma unroll
            for (int r = 0; r < 4; r++) acc[i][j][r] = 0.f;

    auto load_stage = [&](int s, int kb) {
        uint32_t st = sb + s * STG_SZ;
        const __half* pa = A16 + (size_t)m0 * DMODEL + kb * KCH;
        const __half* pb = B16 + (size_t)n0 * DMODEL + kb * KCH;
#pragma unroll
        for (int i = 0; i < 2; i++) {           // A: 1024 segs
            int seg = tid + i * GT;
            int r = seg >> 3, c = seg & 7;
            uint32_t sw = SW128((uint32_t)(r * 128 + c * 16));
            cp_async16(st + sw, pa + (size_t)r * DMODEL + c * 8);
        }
#pragma unroll
        for (int i = 0; i < 4; i++) {           // B: 2048 segs
            int seg = tid + i * GT;
            int r = seg >> 3, c = seg & 7;
            uint32_t sw = SW128((uint32_t)(r * 128 + c * 16));
            cp_async16(st + A_TILE + sw, pb + (size_t)r * DMODEL + c * 8);
        }
        cp_commit();
    };

    load_stage(0, 0);
    load_stage(1, 1);

    int rlane = lane & 15;
    int kc    = lane >> 4;

    // fragment double buffers
    uint32_t fa[2][2][4];      // [buf][mi][4]
    uint32_t fb[2][4][4];      // [buf][jj][4]

    for (int kb = 0; kb < NKB; kb++) {
        int s = kb % 3;
        if (kb + 2 < NKB)      { load_stage((kb + 2) % 3, kb + 2); cp_wait<2>(); }
        else if (kb + 1 < NKB) { cp_wait<1>(); }
        else                   { cp_wait<0>(); }
        __syncthreads();

        uint32_t stA = sb + s * STG_SZ;
        uint32_t stB = stA + A_TILE;

        // prefetch ks=0 fragments
        {
            int koff = kc * 16;
#pragma unroll
            for (int i = 0; i < 2; i++)
                ldm_x4(fa[0][i], stA + SW128((uint32_t)((wm*32 + i*16 + rlane) * 128 + koff)));
#pragma unroll
            for (int jj = 0; jj < 4; jj++)
                ldm_x4(fb[0][jj], stB + SW128((uint32_t)((wn*64 + jj*16 + rlane) * 128 + koff)));
        }

#pragma unroll
        for (int ks = 0; ks < 4; ks++) {
            int cur = ks & 1;
            if (ks < 3) {   // prefetch ks+1 fragments into the other buffer
                int koff = ((ks + 1) * 2 + kc) * 16;
#pragma unroll
                for (int i = 0; i < 2; i++)
                    ldm_x4(fa[cur ^ 1][i], stA + SW128((uint32_t)((wm*32 + i*16 + rlane) * 128 + koff)));
#pragma unroll
                for (int jj = 0; jj < 4; jj++)
                    ldm_x4(fb[cur ^ 1][jj], stB + SW128((uint32_t)((wn*64 + jj*16 + rlane) * 128 + koff)));
            }
#pragma unroll
            for (int jj = 0; jj < 4; jj++)
#pragma unroll
                for (int i = 0; i < 2; i++) {
                    mma16816h(acc[i][2*jj],   fa[cur][i], fb[cur][jj][0], fb[cur][jj][2]);
                    mma16816h(acc[i][2*jj+1], fa[cur][i], fb[cur][jj][1], fb[cur][jj][3]);
                }
        }
        __syncthreads();
    }

    int crow = lane >> 2;
    int ccol = (lane & 3) * 2;
    if (mode == 0) {
#pragma unroll
        for (int i = 0; i < 2; i++) {
            int r0 = m0 + wm*32 + i*16 + crow;
#pragma unroll
            for (int j = 0; j < 8; j++) {
                int n = n0 + wn*64 + j*8 + ccol;
                float b0 = __ldg(bias + n), b1 = __ldg(bias + n + 1);
                *(float2*)(out + (size_t)r0 * DMODEL + n) =
                    make_float2(acc[i][j][0] + b0, acc[i][j][1] + b1);
                *(float2*)(out + (size_t)(r0 + 8) * DMODEL + n) =
                    make_float2(acc[i][j][2] + b0, acc[i][j][3] + b1);
            }
        }
    } else if (mode == 2) {   // single fp16 scatter (V projection)
#pragma unroll
        for (int i = 0; i < 2; i++) {
            int r0 = m0 + wm*32 + i*16 + crow;
            int b_ = r0 >> 11, t0 = r0 & (TSEQ - 1);
#pragma unroll
            for (int j = 0; j < 8; j++) {
                int n = n0 + wn*64 + j*8 + ccol;
                int h = n >> 6, c = n & 63;
                float b0 = __ldg(bias + n), b1 = __ldg(bias + n + 1);
                size_t base = ((size_t)(b_ * NH + h) * TSEQ);
                *(__half2*)(outh + (base + t0) * DK + c) =
                    __halves2half2(__float2half(acc[i][j][0] + b0),
                                   __float2half(acc[i][j][1] + b1));
                *(__half2*)(outh + (base + t0 + 8) * DK + c) =
                    __halves2half2(__float2half(acc[i][j][2] + b0),
                                   __float2half(acc[i][j][3] + b1));
            }
        }
    } else {   // mode 4: bias + RoPE + scale + single fp16 scatter (Q/K)
        int hd = (n0 >> 6) + wn;            // warp n-tile == one head
#pragma unroll
        for (int i = 0; i < 2; i++) {
            int r0 = m0 + wm*32 + i*16 + crow;
            int b_ = r0 >> 11, t0 = r0 & (TSEQ - 1);
            size_t base0 = (((size_t)(b_ * NH + hd) * TSEQ) + t0) * DK;
            size_t base1 = base0 + 8 * DK;
#pragma unroll
            for (int j = 0; j < 4; j++) {   // pair columns (c, c+32)
                int c = j*8 + ccol;
                float b0 = __ldg(bias + hd*64 + c);
                float b1 = __ldg(bias + hd*64 + c + 1);
                float b2 = __ldg(bias + hd*64 + c + 32);
                float b3 = __ldg(bias + hd*64 + c + 33);
                float2 cs0 = g_rope[t0*32 + c];
                float2 cs1 = g_rope[t0*32 + c + 1];
                float2 cs2 = g_rope[(t0+8)*32 + c];
                float2 cs3 = g_rope[(t0+8)*32 + c + 1];
                float x0 = acc[i][j][0] + b0,   x1 = acc[i][j][1] + b1;
                float y0 = acc[i][j+4][0] + b2, y1 = acc[i][j+4][1] + b3;
                float o0 = (x0*cs0.x - y0*cs0.y) * scale;
                float o1 = (x1*cs1.x - y1*cs1.y) * scale;
                float p0 = (y0*cs0.x + x0*cs0.y) * scale;
                float p1 = (y1*cs1.x + x1*cs1.y) * scale;
                float x2 = acc[i][j][2] + b0,   x3 = acc[i][j][3] + b1;
                float y2 = acc[i][j+4][2] + b2, y3 = acc[i][j+4][3] + b3;
                float o2 = (x2*cs2.x - y2*cs2.y) * scale;
                float o3 = (x3*cs3.x - y3*cs3.y) * scale;
                float p2 = (y2*cs2.x + x2*cs2.y) * scale;
                float p3 = (y3*cs3.x + x3*cs3.y) * scale;

                *(__half2*)(outh + base0 + c)      = __halves2half2(__float2half(o0), __float2half(o1));
                *(__half2*)(outh + base0 + c + 32) = __halves2half2(__float2half(p0), __float2half(p1));
                *(__half2*)(outh + base1 + c)      = __halves2half2(__float2half(o2), __float2half(o3));
                *(__half2*)(outh + base1 + c + 32) = __halves2half2(__float2half(p2), __float2half(p3));
            }
        }
    }
}

// fused QKV: blockIdx.z selects weight/output set. Q/K get fused RoPE.
__global__ __launch_bounds__(GT, 1)
void gemm_qkv(const float* __restrict__ bq, const float* __restrict__ bk,
              const float* __restrict__ bv)
{
    extern __shared__ char smem[];
    int m0 = blockIdx.y * 128;
    int n0 = blockIdx.x * 256;
    int z = blockIdx.z;
    if (z == 0)
        gemm_core(g_A16, g_Wq16, bq, 0, g_Q16, 4, 0.125f, smem, m0, n0);
    else if (z == 1)
        gemm_core(g_A16, g_Wk16, bk, 0, g_K16, 4, 1.0f, smem, m0, n0);
    else
        gemm_core(g_A16, g_Wv16, bv, 0, g_V16, 2, 1.0f, smem, m0, n0);
}

// output projection
__global__ __launch_bounds__(GT, 1)
void gemm_out(const float* __restrict__ bias, float* __restrict__ out)
{
    extern __shared__ char smem[];
    gemm_core(g_O16, g_Wo16, bias, out, 0, 0, 1.0f, smem,
              blockIdx.y * 128, blockIdx.x * 256);
}

// =========================================================================
// fp16 flash attention (unchanged from R15). CTA = 128 queries x 8 warps,
// 2 CTAs/SM. K-tile 64, triple buffered. Q,K,V,P single fp16.
// =========================================================================
#define A2_Q    0
#define A2_STG  16384
#define A2_STGS 16384     // per stage: K 8K | V 8K
#define A2_MASK 65536     // 16384 + 3*16384
#define A2_SMEM (A2_MASK + TSEQ*4)   // 73728  (x2 CTAs = 147456)

__global__ __launch_bounds__(256, 2)
void attn_hmma(const unsigned char* __restrict__ mask)
{
    extern __shared__ char smem[];
    uint32_t sb = smem_u32(smem);
    int tid = threadIdx.x, lane = tid & 31, wid = tid >> 5;
    int bh = blockIdx.y, b = bh >> 4, h = bh & 15;
    int q0 = blockIdx.x * 128;
    int rlane = lane & 15, kc = lane >> 4;

    {   // Q tile (single), group 0
        size_t qb = ((size_t)bh * TSEQ + q0) * DK;
#pragma unroll
        for (int i = 0; i < 4; i++) {
            int seg = tid + i * 256;
            int r = seg >> 3, c = seg & 7;
            uint32_t sw = SW128((uint32_t)(r * 128 + c * 16));
            cp_async16(sb + A2_Q + sw, g_Q16 + qb + (size_t)r * DK + c * 8);
        }
        cp_commit();
    }
    auto load_stage = [&](int s, int kt) {
        uint32_t st = sb + A2_STG + s * A2_STGS;
        size_t base = ((size_t)bh * TSEQ + kt * 64) * DK;
#pragma unroll
        for (int i = 0; i < 2; i++) {
            int seg = tid + i * 256;
            int r = seg >> 3, c = seg & 7;
            uint32_t sw = SW128((uint32_t)(r * 128 + c * 16));
            size_t go = base + (size_t)r * DK + c * 8;
            cp_async16(st + sw,        g_K16 + go);
            cp_async16(st + 8192 + sw, g_V16 + go);
        }
        cp_commit();
    };
    load_stage(0, 0);
    load_stage(1, 1);

    {   // mask -> additive fp32 bias row
        const unsigned char* mkp = mask + (size_t)b * TSEQ;
        float* msk = (float*)(smem + A2_MASK);
#pragma unroll
        for (int i = 0; i < 8; i++) {
            int t = tid * 8 + i;
            msk[t] = mkp[t] ? -1e30f : 0.f;
        }
    }

    cp_wait<2>();      // Q group done (stages 0,1 may be outstanding)
    __syncthreads();

    uint32_t aq[4][4];
#pragma unroll
    for (int ks = 0; ks < 4; ks++) {
        uint32_t off = SW128((uint32_t)((wid*16 + rlane) * 128 + (ks*2 + kc) * 16));
        ldm_x4(aq[ks], sb + A2_Q + off);
    }

    float m0 = -1e30f, m1 = -1e30f, l0 = 0.f, l1 = 0.f;
    float o[8][4];
#pragma unroll
    for (int j = 0; j < 8; j++)
#pragma unroll
        for (int r = 0; r < 4; r++) o[j][r] = 0.f;

    const float* msk = (const float*)(smem + A2_MASK);

    for (int kt = 0; kt < 32; kt++) {
        int s = kt % 3;
        if (kt + 2 < 32)      { load_stage((kt + 2) % 3, kt + 2); cp_wait<2>(); }
        else if (kt + 1 < 32) { cp_wait<1>(); }
        else                  { cp_wait<0>(); }
        __syncthreads();

        uint32_t stK = sb + A2_STG + s * A2_STGS;
        uint32_t stV = stK + 8192;

        float sv[8][4];
#pragma unroll
        for (int j = 0; j < 8; j++)
#pragma unroll
            for (int r = 0; r < 4; r++) sv[j][r] = 0.f;

#pragma unroll
        for (int ks = 0; ks < 4; ks++) {
            int koff = (ks*2 + kc) * 16;
            uint32_t bk[8][2];
#pragma unroll
            for (int jj = 0; jj < 4; jj++) {
                uint32_t off = SW128((uint32_t)((jj*16 + rlane) * 128 + koff));
                uint32_t r[4];
                ldm_x4(r, stK + off);
                bk[2*jj][0] = r[0]; bk[2*jj+1][0] = r[1];
                bk[2*jj][1] = r[2]; bk[2*jj+1][1] = r[3];
            }
#pragma unroll
            for (int j = 0; j < 8; j++)
                mma16816h(sv[j], aq[ks], bk[j][0], bk[j][1]);
        }

        int mbase = kt * 64 + (lane & 3) * 2;
#pragma unroll
        for (int j = 0; j < 8; j++) {
            float mb0 = msk[mbase + j*8], mb1 = msk[mbase + j*8 + 1];
            sv[j][0] += mb0; sv[j][1] += mb1;
            sv[j][2] += mb0; sv[j][3] += mb1;
        }
        float mx0 = -1e30f, mx1 = -1e30f;
#pragma unroll
        for (int j = 0; j < 8; j++) {
            mx0 = fmaxf(mx0, fmaxf(sv[j][0], sv[j][1]));
            mx1 = fmaxf(mx1, fmaxf(sv[j][2], sv[j][3]));
        }
        mx0 = fmaxf(mx0, __shfl_xor_sync(0xffffffffu, mx0, 1));
        mx0 = fmaxf(mx0, __shfl_xor_sync(0xffffffffu, mx0, 2));
        mx1 = fmaxf(mx1, __shfl_xor_sync(0xffffffffu, mx1, 1));
        mx1 = fmaxf(mx1, __shfl_xor_sync(0xffffffffu, mx1, 2));
        float mn0 = fmaxf(m0, mx0), mn1 = fmaxf(m1, mx1);
        float al0 = __expf(m0 - mn0), al1 = __expf(m1 - mn1);
        m0 = mn0; m1 = mn1;

        float ls0 = 0.f, ls1 = 0.f;
        uint32_t pha[8], phb[8];
#pragma unroll
        for (int j = 0; j < 8; j++) {
            float p0 = __expf(sv[j][0] - mn0);
            float p1 = __expf(sv[j][1] - mn0);
            float p2 = __expf(sv[j][2] - mn1);
            float p3 = __expf(sv[j][3] - mn1);
            ls0 += p0 + p1;  ls1 += p2 + p3;
            pha[j] = packh2(__float2half(p0), __float2half(p1));
            phb[j] = packh2(__float2half(p2), __float2half(p3));
        }
        l0 = l0 * al0 + ls0;
        l1 = l1 * al1 + ls1;
#pragma unroll
        for (int j = 0; j < 8; j++) {
            o[j][0] *= al0; o[j][1] *= al0;
            o[j][2] *= al1; o[j][3] *= al1;
        }

#pragma unroll
        for (int ks = 0; ks < 4; ks++) {
            uint32_t pa_h[4] = {pha[2*ks], phb[2*ks], pha[2*ks+1], phb[2*ks+1]};
            uint32_t bv[8][2];
#pragma unroll
            for (int jj = 0; jj < 4; jj++) {
                uint32_t off = SW128((uint32_t)((ks*16 + rlane) * 128 + (jj*2 + kc) * 16));
                uint32_t r[4];
                ldm_x4_t(r, stV + off);
                bv[2*jj][0] = r[0]; bv[2*jj][1] = r[1];
                bv[2*jj+1][0] = r[2]; bv[2*jj+1][1] = r[3];
            }
#pragma unroll
            for (int j = 0; j < 8; j++)
                mma16816h(o[j], pa_h, bv[j][0], bv[j][1]);
        }
        __syncthreads();
    }

    l0 += __shfl_xor_sync(0xffffffffu, l0, 1);
    l0 += __shfl_xor_sync(0xffffffffu, l0, 2);
    l1 += __shfl_xor_sync(0xffffffffu, l1, 1);
    l1 += __shfl_xor_sync(0xffffffffu, l1, 2);
    float inv0 = 1.f / l0, inv1 = 1.f / l1;

    int row0 = q0 + wid * 16 + (lane >> 2);
    int colb = h * DK + (lane & 3) * 2;
#pragma unroll
    for (int j = 0; j < 8; j++) {
        int col = colb + j * 8;
        size_t i0 = ((size_t)(b * TSEQ + row0)) * DMODEL + col;
        size_t i1 = ((size_t)(b * TSEQ + row0 + 8)) * DMODEL + col;
        *(__half2*)&g_O16[i0] = __halves2half2(__float2half(o[j][0] * inv0),
                                               __float2half(o[j][1] * inv0));
        *(__half2*)&g_O16[i1] = __halves2half2(__float2half(o[j][2] * inv1),
                                               __float2half(o[j][3] * inv1));
    }
}

// =========================================================================
// launch
// =========================================================================
extern "C" void kernel_launch(void* const* d_in, const int* in_sizes, int n_in,
                              void* d_out, int out_size)
{
    const float* x          = (const float*)d_in[0];
    const unsigned char* mk = (const unsigned char*)d_in[1];
    const float* Wq = (const float*)d_in[2];
    const float* bq = (const float*)d_in[3];
    const float* Wk = (const float*)d_in[4];
    const float* bk = (const float*)d_in[5];
    const float* Wv = (const float*)d_in[6];
    const float* bv = (const float*)d_in[7];
    const float* Wo = (const float*)d_in[8];
    const float* bo = (const float*)d_in[9];
    float* out = (float*)d_out;

    __half* a16;
    cudaGetSymbolAddress((void**)&a16, g_A16);

    cudaFuncSetAttribute(gemm_qkv, cudaFuncAttributeMaxDynamicSharedMemorySize, GEMM_SMEM);
    cudaFuncSetAttribute(gemm_out, cudaFuncAttributeMaxDynamicSharedMemorySize, GEMM_SMEM);
    cudaFuncSetAttribute(attn_hmma, cudaFuncAttributeMaxDynamicSharedMemorySize, A2_SMEM);

    const int NW = DMODEL * DMODEL;   // 1048576
    const int NX = MROWS * DMODEL;    // 8388608

    quant_kernel<<<NX / 1024, 256>>>(x, a16, NX);
    dim3 gw(NW / 1024, 1, 4);
    quant_w4<<<gw, 256>>>(Wq, Wk, Wv, Wo, NW);
    rope_table_kernel<<<(TSEQ * 32) / 256, 256>>>();

    dim3 gq(DMODEL / 256, MROWS / 128, 3);   // (4, 64, 3)
    gemm_qkv<<<gq, GT, GEMM_SMEM>>>(bq, bk, bv);

    dim3 ag(TSEQ / 128, BSZ * NH);           // (16, 64)
    attn_hmma<<<ag, 256, A2_SMEM>>>(mk);

    dim3 go(DMODEL / 256, MROWS / 128);      // (4, 64)
    gemm_out<<<go, GT, GEMM_SMEM>>>(bo, out);
}

// round 17
// speedup vs baseline: 1.0329x; 1.0329x over previous
#include <cuda_runtime.h>
#include <cuda_fp16.h>
#include <math.h>
#include <stdint.h>

// ---------------- problem constants ----------------
#define BSZ    4
#define TSEQ   2048
#define DMODEL 1024
#define NH     16
#define DK     64
#define MROWS  (BSZ*TSEQ)          // 8192
#define QKV_ELEMS (BSZ*NH*TSEQ*DK) // 8388608

// ---------------- scratch (static device globals) ----------------
__device__ __half g_A16[MROWS*DMODEL];       // x quantized fp16 (QKV GEMM A)
__device__ __half g_O16[MROWS*DMODEL];       // attention output fp16 (out GEMM A)
__device__ __half g_Q16[QKV_ELEMS];          // Q fp16 single (pre-scaled)
__device__ __half g_K16[QKV_ELEMS];          // K fp16 single
__device__ __half g_V16[QKV_ELEMS];          // V fp16 single
__device__ __half g_Wq16[DMODEL*DMODEL], g_Wk16[DMODEL*DMODEL];
__device__ __half g_Wv16[DMODEL*DMODEL], g_Wo16[DMODEL*DMODEL];
__device__ float2 g_rope[TSEQ*32];           // (cos, sin) per (t, pair)

// =========================================================================
// PTX helpers
// =========================================================================
__device__ __forceinline__ uint32_t smem_u32(const void* p) {
    uint32_t a;
    asm("{ .reg .u64 t; cvta.to.shared.u64 t, %1; cvt.u32.u64 %0, t; }"
        : "=r"(a) : "l"(p));
    return a;
}
#define SW128(off) ((off) ^ (((off) >> 3) & 0x70))

__device__ __forceinline__ void cp_async16(uint32_t s, const void* g) {
    asm volatile("cp.async.cg.shared.global [%0], [%1], 16;" :: "r"(s), "l"(g));
}
__device__ __forceinline__ void cp_commit() {
    asm volatile("cp.async.commit_group;" ::: "memory");
}
template <int N> __device__ __forceinline__ void cp_wait() {
    asm volatile("cp.async.wait_group %0;" :: "n"(N) : "memory");
}

__device__ __forceinline__ void ldm_x4(uint32_t* r, uint32_t addr) {
    asm volatile("ldmatrix.sync.aligned.m8n8.x4.shared.b16 {%0,%1,%2,%3}, [%4];"
        : "=r"(r[0]), "=r"(r[1]), "=r"(r[2]), "=r"(r[3]) : "r"(addr));
}
__device__ __forceinline__ void ldm_x4_t(uint32_t* r, uint32_t addr) {
    asm volatile("ldmatrix.sync.aligned.m8n8.x4.trans.shared.b16 {%0,%1,%2,%3}, [%4];"
        : "=r"(r[0]), "=r"(r[1]), "=r"(r[2]), "=r"(r[3]) : "r"(addr));
}

__device__ __forceinline__ void mma16816h(float* c, const uint32_t* a,
                                          uint32_t b0, uint32_t b1) {
    asm volatile(
        "mma.sync.aligned.m16n8k16.row.col.f32.f16.f16.f32 "
        "{%0,%1,%2,%3}, {%4,%5,%6,%7}, {%8,%9}, {%0,%1,%2,%3};"
        : "+f"(c[0]), "+f"(c[1]), "+f"(c[2]), "+f"(c[3])
        : "r"(a[0]), "r"(a[1]), "r"(a[2]), "r"(a[3]), "r"(b0), "r"(b1));
}

__device__ __forceinline__ uint32_t packh2(__half a, __half b) {
    __half2 t = __halves2half2(a, b);
    return *reinterpret_cast<uint32_t*>(&t);
}

// =========================================================================
// fused preprocessing: one launch.
//   blocks [0, 8192)      : x -> g_A16       (1024 elems/block)
//   blocks [8192, 12288)  : W{q,k,v,o} -> fp16 (1024 elems/block each 1024 blocks)
//   blocks [12288, 12544) : rope table       (256 entries/block)
// =========================================================================
#define XB 8192
#define WB 1024
__global__ void prep_kernel(const float* __restrict__ x,
                            const float* __restrict__ w0, const float* __restrict__ w1,
                            const float* __restrict__ w2, const float* __restrict__ w3)
{
    int blk = blockIdx.x;
    if (blk < XB + 4*WB) {
        const float* src;
        __half* dst;
        int base;
        if (blk < XB) { src = x; dst = g_A16; base = blk; }
        else {
            int wi = (blk - XB) >> 10;        // 0..3
            base = (blk - XB) & (WB - 1);
            switch (wi) {
                case 0: src = w0; dst = g_Wq16; break;
                case 1: src = w1; dst = g_Wk16; break;
                case 2: src = w2; dst = g_Wv16; break;
                default: src = w3; dst = g_Wo16; break;
            }
        }
        int i = base * 1024 + threadIdx.x * 4;
        float4 v = *(const float4*)(src + i);
        *(__half2*)(dst + i)     = __halves2half2(__float2half(v.x), __float2half(v.y));
        *(__half2*)(dst + i + 2) = __halves2half2(__float2half(v.z), __float2half(v.w));
    } else {
        int idx = (blk - XB - 4*WB) * 256 + threadIdx.x;   // 0..65535
        int c = idx & 31, t = idx >> 5;
        float invf = exp2f(-(float)c * (0.03125f * 13.287712379549449f));
        float s, cs;
        sincosf((float)t * invf, &s, &cs);
        g_rope[idx] = make_float2(cs, s);
    }
}

// =========================================================================
// pure fp16 GEMM core (R15 form): C = A16 * B16^T + bias.
// CTA 128m x 256n, K-chunk 64, TRIPLE buffered cp.async.
// 512 threads, 16 warps in 4(m) x 4(n), warp tile 32x64.
// =========================================================================
#define KCH 64
#define NKB (DMODEL / KCH)        // 16
#define A_TILE 16384              // 128 rows * 128B
#define B_TILE 32768              // 256 rows * 128B
#define STG_SZ (A_TILE + B_TILE)      // 49152
#define GEMM_SMEM (3 * STG_SZ)        // 147456
#define GT 512

__device__ __forceinline__ void gemm_core(
    const __half* __restrict__ A16, const __half* __restrict__ B16,
    const float* __restrict__ bias, float* __restrict__ out,
    __half* __restrict__ outh,
    int mode, float scale, char* smem, int m0, int n0)
{
    uint32_t sb = smem_u32(smem);
    int tid = threadIdx.x, lane = tid & 31, wid = tid >> 5;   // 0..15
    int wm = wid & 3, wn = wid >> 2;      // 4(m) x 4(n), warp tile 32x64

    float acc[2][8][4];
#pragma unroll
    for (int i = 0; i < 2; i++)
#pragma unroll
        for (int j = 0; j < 8; j++)
#pragma unroll
            for (int r = 0; r < 4; r++) acc[i][j][r] = 0.f;

    auto load_stage = [&](int s, int kb) {
        uint32_t st = sb + s * STG_SZ;
        const __half* pa = A16 + (size_t)m0 * DMODEL + kb * KCH;
        const __half* pb = B16 + (size_t)n0 * DMODEL + kb * KCH;
#pragma unroll
        for (int i = 0; i < 2; i++) {           // A: 1024 segs
            int seg = tid + i * GT;
            int r = seg >> 3, c = seg & 7;
            uint32_t sw = SW128((uint32_t)(r * 128 + c * 16));
            cp_async16(st + sw, pa + (size_t)r * DMODEL + c * 8);
        }
#pragma unroll
        for (int i = 0; i < 4; i++) {           // B: 2048 segs
            int seg = tid + i * GT;
            int r = seg >> 3, c = seg & 7;
            uint32_t sw = SW128((uint32_t)(r * 128 + c * 16));
            cp_async16(st + A_TILE + sw, pb + (size_t)r * DMODEL + c * 8);
        }
        cp_commit();
    };

    load_stage(0, 0);
    load_stage(1, 1);

    int rlane = lane & 15;
    int kc    = lane >> 4;

    for (int kb = 0; kb < NKB; kb++) {
        int s = kb % 3;
        if (kb + 2 < NKB)      { load_stage((kb + 2) % 3, kb + 2); cp_wait<2>(); }
        else if (kb + 1 < NKB) { cp_wait<1>(); }
        else                   { cp_wait<0>(); }
        __syncthreads();

        uint32_t stA = sb + s * STG_SZ;
        uint32_t stB = stA + A_TILE;

#pragma unroll
        for (int ks = 0; ks < 4; ks++) {
            int koff = (ks * 2 + kc) * 16;
            uint32_t a[2][4];
#pragma unroll
            for (int i = 0; i < 2; i++) {
                uint32_t off = SW128((uint32_t)((wm*32 + i*16 + rlane) * 128 + koff));
                ldm_x4(a[i], stA + off);
            }
#pragma unroll
            for (int jj = 0; jj < 4; jj++) {    // 2 n8-tiles per jj
                uint32_t off = SW128((uint32_t)((wn*64 + jj*16 + rlane) * 128 + koff));
                uint32_t rh[4];
                ldm_x4(rh, stB + off);
#pragma unroll
                for (int i = 0; i < 2; i++) {
                    mma16816h(acc[i][2*jj],   a[i], rh[0], rh[2]);
                    mma16816h(acc[i][2*jj+1], a[i], rh[1], rh[3]);
                }
            }
        }
        __syncthreads();
    }

    int crow = lane >> 2;
    int ccol = (lane & 3) * 2;
    if (mode == 0) {
#pragma unroll
        for (int i = 0; i < 2; i++) {
            int r0 = m0 + wm*32 + i*16 + crow;
#pragma unroll
            for (int j = 0; j < 8; j++) {
                int n = n0 + wn*64 + j*8 + ccol;
                float b0 = __ldg(bias + n), b1 = __ldg(bias + n + 1);
                *(float2*)(out + (size_t)r0 * DMODEL + n) =
                    make_float2(acc[i][j][0] + b0, acc[i][j][1] + b1);
                *(float2*)(out + (size_t)(r0 + 8) * DMODEL + n) =
                    make_float2(acc[i][j][2] + b0, acc[i][j][3] + b1);
            }
        }
    } else if (mode == 2) {   // single fp16 scatter (V projection)
#pragma unroll
        for (int i = 0; i < 2; i++) {
            int r0 = m0 + wm*32 + i*16 + crow;
            int b_ = r0 >> 11, t0 = r0 & (TSEQ - 1);
#pragma unroll
            for (int j = 0; j < 8; j++) {
                int n = n0 + wn*64 + j*8 + ccol;
                int h = n >> 6, c = n & 63;
                float b0 = __ldg(bias + n), b1 = __ldg(bias + n + 1);
                size_t base = ((size_t)(b_ * NH + h) * TSEQ);
                *(__half2*)(outh + (base + t0) * DK + c) =
                    __halves2half2(__float2half(acc[i][j][0] + b0),
                                   __float2half(acc[i][j][1] + b1));
                *(__half2*)(outh + (base + t0 + 8) * DK + c) =
                    __halves2half2(__float2half(acc[i][j][2] + b0),
                                   __float2half(acc[i][j][3] + b1));
            }
        }
    } else {   // mode 4: bias + RoPE + scale + single fp16 scatter (Q/K)
        int hd = (n0 >> 6) + wn;            // warp n-tile == one head
#pragma unroll
        for (int i = 0; i < 2; i++) {
            int r0 = m0 + wm*32 + i*16 + crow;
            int b_ = r0 >> 11, t0 = r0 & (TSEQ - 1);
            size_t base0 = (((size_t)(b_ * NH + hd) * TSEQ) + t0) * DK;
            size_t base1 = base0 + 8 * DK;
#pragma unroll
            for (int j = 0; j < 4; j++) {   // pair columns (c, c+32)
                int c = j*8 + ccol;
                float b0 = __ldg(bias + hd*64 + c);
                float b1 = __ldg(bias + hd*64 + c + 1);
                float b2 = __ldg(bias + hd*64 + c + 32);
                float b3 = __ldg(bias + hd*64 + c + 33);
                float2 cs0 = g_rope[t0*32 + c];
                float2 cs1 = g_rope[t0*32 + c + 1];
                float2 cs2 = g_rope[(t0+8)*32 + c];
                float2 cs3 = g_rope[(t0+8)*32 + c + 1];
                float x0 = acc[i][j][0] + b0,   x1 = acc[i][j][1] + b1;
                float y0 = acc[i][j+4][0] + b2, y1 = acc[i][j+4][1] + b3;
                float o0 = (x0*cs0.x - y0*cs0.y) * scale;
                float o1 = (x1*cs1.x - y1*cs1.y) * scale;
                float p0 = (y0*cs0.x + x0*cs0.y) * scale;
                float p1 = (y1*cs1.x + x1*cs1.y) * scale;
                float x2 = acc[i][j][2] + b0,   x3 = acc[i][j][3] + b1;
                float y2 = acc[i][j+4][2] + b2, y3 = acc[i][j+4][3] + b3;
                float o2 = (x2*cs2.x - y2*cs2.y) * scale;
                float o3 = (x3*cs3.x - y3*cs3.y) * scale;
                float p2 = (y2*cs2.x + x2*cs2.y) * scale;
                float p3 = (y3*cs3.x + x3*cs3.y) * scale;

                *(__half2*)(outh + base0 + c)      = __halves2half2(__float2half(o0), __float2half(o1));
                *(__half2*)(outh + base0 + c + 32) = __halves2half2(__float2half(p0), __float2half(p1));
                *(__half2*)(outh + base1 + c)      = __halves2half2(__float2half(o2), __float2half(o3));
                *(__half2*)(outh + base1 + c + 32) = __halves2half2(__float2half(p2), __float2half(p3));
            }
        }
    }
}

// fused QKV: blockIdx.z selects weight/output set. Q/K get fused RoPE.
__global__ __launch_bounds__(GT, 1)
void gemm_qkv(const float* __restrict__ bq, const float* __restrict__ bk,
              const float* __restrict__ bv)
{
    extern __shared__ char smem[];
    int m0 = blockIdx.y * 128;
    int n0 = blockIdx.x * 256;
    int z = blockIdx.z;
    if (z == 0)
        gemm_core(g_A16, g_Wq16, bq, 0, g_Q16, 4, 0.125f, smem, m0, n0);
    else if (z == 1)
        gemm_core(g_A16, g_Wk16, bk, 0, g_K16, 4, 1.0f, smem, m0, n0);
    else
        gemm_core(g_A16, g_Wv16, bv, 0, g_V16, 2, 1.0f, smem, m0, n0);
}

// output projection
__global__ __launch_bounds__(GT, 1)
void gemm_out(const float* __restrict__ bias, float* __restrict__ out)
{
    extern __shared__ char smem[];
    gemm_core(g_O16, g_Wo16, bias, out, 0, 0, 1.0f, smem,
              blockIdx.y * 128, blockIdx.x * 256);
}

// =========================================================================
// fp16 flash attention (R15 form). CTA = 128 queries x 8 warps, 2 CTAs/SM.
// K-tile 64, triple buffered (16KB/stage). Q,K,V,P single fp16.
// =========================================================================
#define A2_Q    0
#define A2_STG  16384
#define A2_STGS 16384     // per stage: K 8K | V 8K
#define A2_MASK 65536     // 16384 + 3*16384
#define A2_SMEM (A2_MASK + TSEQ*4)   // 73728  (x2 CTAs = 147456)

__global__ __launch_bounds__(256, 2)
void attn_hmma(const unsigned char* __restrict__ mask)
{
    extern __shared__ char smem[];
    uint32_t sb = smem_u32(smem);
    int tid = threadIdx.x, lane = tid & 31, wid = tid >> 5;
    int bh = blockIdx.y, b = bh >> 4, h = bh & 15;
    int q0 = blockIdx.x * 128;
    int rlane = lane & 15, kc = lane >> 4;

    {   // Q tile (single), group 0
        size_t qb = ((size_t)bh * TSEQ + q0) * DK;
#pragma unroll
        for (int i = 0; i < 4; i++) {
            int seg = tid + i * 256;
            int r = seg >> 3, c = seg & 7;
            uint32_t sw = SW128((uint32_t)(r * 128 + c * 16));
            cp_async16(sb + A2_Q + sw, g_Q16 + qb + (size_t)r * DK + c * 8);
        }
        cp_commit();
    }
    auto load_stage = [&](int s, int kt) {
        uint32_t st = sb + A2_STG + s * A2_STGS;
        size_t base = ((size_t)bh * TSEQ + kt * 64) * DK;
#pragma unroll
        for (int i = 0; i < 2; i++) {
            int seg = tid + i * 256;
            int r = seg >> 3, c = seg & 7;
            uint32_t sw = SW128((uint32_t)(r * 128 + c * 16));
            size_t go = base + (size_t)r * DK + c * 8;
            cp_async16(st + sw,        g_K16 + go);
            cp_async16(st + 8192 + sw, g_V16 + go);
        }
        cp_commit();
    };
    load_stage(0, 0);
    load_stage(1, 1);

    {   // mask -> additive fp32 bias row
        const unsigned char* mkp = mask + (size_t)b * TSEQ;
        float* msk = (float*)(smem + A2_MASK);
#pragma unroll
        for (int i = 0; i < 8; i++) {
            int t = tid * 8 + i;
            msk[t] = mkp[t] ? -1e30f : 0.f;
        }
    }

    cp_wait<2>();      // Q group done (stages 0,1 may be outstanding)
    __syncthreads();

    uint32_t aq[4][4];
#pragma unroll
    for (int ks = 0; ks < 4; ks++) {
        uint32_t off = SW128((uint32_t)((wid*16 + rlane) * 128 + (ks*2 + kc) * 16));
        ldm_x4(aq[ks], sb + A2_Q + off);
    }

    float m0 = -1e30f, m1 = -1e30f, l0 = 0.f, l1 = 0.f;
    float o[8][4];
#pragma unroll
    for (int j = 0; j < 8; j++)
#pragma unroll
        for (int r = 0; r < 4; r++) o[j][r] = 0.f;

    const float* msk = (const float*)(smem + A2_MASK);

    for (int kt = 0; kt < 32; kt++) {
        int s = kt % 3;
        if (kt + 2 < 32)      { load_stage((kt + 2) % 3, kt + 2); cp_wait<2>(); }
        else if (kt + 1 < 32) { cp_wait<1>(); }
        else                  { cp_wait<0>(); }
        __syncthreads();

        uint32_t stK = sb + A2_STG + s * A2_STGS;
        uint32_t stV = stK + 8192;

        float sv[8][4];
#pragma unroll
        for (int j = 0; j < 8; j++)
#pragma unroll
            for (int r = 0; r < 4; r++) sv[j][r] = 0.f;

#pragma unroll
        for (int ks = 0; ks < 4; ks++) {
            int koff = (ks*2 + kc) * 16;
            uint32_t bk[8][2];
#pragma unroll
            for (int jj = 0; jj < 4; jj++) {
                uint32_t off = SW128((uint32_t)((jj*16 + rlane) * 128 + koff));
                uint32_t r[4];
                ldm_x4(r, stK + off);
                bk[2*jj][0] = r[0]; bk[2*jj+1][0] = r[1];
                bk[2*jj][1] = r[2]; bk[2*jj+1][1] = r[3];
            }
#pragma unroll
            for (int j = 0; j < 8; j++)
                mma16816h(sv[j], aq[ks], bk[j][0], bk[j][1]);
        }

        int mbase = kt * 64 + (lane & 3) * 2;
#pragma unroll
        for (int j = 0; j < 8; j++) {
            float mb0 = msk[mbase + j*8], mb1 = msk[mbase + j*8 + 1];
            sv[j][0] += mb0; sv[j][1] += mb1;
            sv[j][2] += mb0; sv[j][3] += mb1;
        }
        float mx0 = -1e30f, mx1 = -1e30f;
#pragma unroll
        for (int j = 0; j < 8; j++) {
            mx0 = fmaxf(mx0, fmaxf(sv[j][0], sv[j][1]));
            mx1 = fmaxf(mx1, fmaxf(sv[j][2], sv[j][3]));
        }
        mx0 = fmaxf(mx0, __shfl_xor_sync(0xffffffffu, mx0, 1));
        mx0 = fmaxf(mx0, __shfl_xor_sync(0xffffffffu, mx0, 2));
        mx1 = fmaxf(mx1, __shfl_xor_sync(0xffffffffu, mx1, 1));
        mx1 = fmaxf(mx1, __shfl_xor_sync(0xffffffffu, mx1, 2));
        float mn0 = fmaxf(m0, mx0), mn1 = fmaxf(m1, mx1);
        float al0 = __expf(m0 - mn0), al1 = __expf(m1 - mn1);
        m0 = mn0; m1 = mn1;

        float ls0 = 0.f, ls1 = 0.f;
        uint32_t pha[8], phb[8];
#pragma unroll
        for (int j = 0; j < 8; j++) {
            float p0 = __expf(sv[j][0] - mn0);
            float p1 = __expf(sv[j][1] - mn0);
            float p2 = __expf(sv[j][2] - mn1);
            float p3 = __expf(sv[j][3] - mn1);
            ls0 += p0 + p1;  ls1 += p2 + p3;
            pha[j] = packh2(__float2half(p0), __float2half(p1));
            phb[j] = packh2(__float2half(p2), __float2half(p3));
        }
        l0 = l0 * al0 + ls0;
        l1 = l1 * al1 + ls1;
#pragma unroll
        for (int j = 0; j < 8; j++) {
            o[j][0] *= al0; o[j][1] *= al0;
            o[j][2] *= al1; o[j][3] *= al1;
        }

#pragma unroll
        for (int ks = 0; ks < 4; ks++) {
            uint32_t pa_h[4] = {pha[2*ks], phb[2*ks], pha[2*ks+1], phb[2*ks+1]};
            uint32_t bv[8][2];
#pragma unroll
            for (int jj = 0; jj < 4; jj++) {
                uint32_t off = SW128((uint32_t)((ks*16 + rlane) * 128 + (jj*2 + kc) * 16));
                uint32_t r[4];
                ldm_x4_t(r, stV + off);
                bv[2*jj][0] = r[0]; bv[2*jj][1] = r[1];
                bv[2*jj+1][0] = r[2]; bv[2*jj+1][1] = r[3];
            }
#pragma unroll
            for (int j = 0; j < 8; j++)
                mma16816h(o[j], pa_h, bv[j][0], bv[j][1]);
        }
        __syncthreads();
    }

    l0 += __shfl_xor_sync(0xffffffffu, l0, 1);
    l0 += __shfl_xor_sync(0xffffffffu, l0, 2);
    l1 += __shfl_xor_sync(0xffffffffu, l1, 1);
    l1 += __shfl_xor_sync(0xffffffffu, l1, 2);
    float inv0 = 1.f / l0, inv1 = 1.f / l1;

    int row0 = q0 + wid * 16 + (lane >> 2);
    int colb = h * DK + (lane & 3) * 2;
#pragma unroll
    for (int j = 0; j < 8; j++) {
        int col = colb + j * 8;
        size_t i0 = ((size_t)(b * TSEQ + row0)) * DMODEL + col;
        size_t i1 = ((size_t)(b * TSEQ + row0 + 8)) * DMODEL + col;
        *(__half2*)&g_O16[i0] = __halves2half2(__float2half(o[j][0] * inv0),
                                               __float2half(o[j][1] * inv0));
        *(__half2*)&g_O16[i1] = __halves2half2(__float2half(o[j][2] * inv1),
                                               __float2half(o[j][3] * inv1));
    }
}

// =========================================================================
// launch
// =========================================================================
extern "C" void kernel_launch(void* const* d_in, const int* in_sizes, int n_in,
                              void* d_out, int out_size)
{
    const float* x          = (const float*)d_in[0];
    const unsigned char* mk = (const unsigned char*)d_in[1];
    const float* Wq = (const float*)d_in[2];
    const float* bq = (const float*)d_in[3];
    const float* Wk = (const float*)d_in[4];
    const float* bk = (const float*)d_in[5];
    const float* Wv = (const float*)d_in[6];
    const float* bv = (const float*)d_in[7];
    const float* Wo = (const float*)d_in[8];
    const float* bo = (const float*)d_in[9];
    float* out = (float*)d_out;

    cudaFuncSetAttribute(gemm_qkv, cudaFuncAttributeMaxDynamicSharedMemorySize, GEMM_SMEM);
    cudaFuncSetAttribute(gemm_out, cudaFuncAttributeMaxDynamicSharedMemorySize, GEMM_SMEM);
    cudaFuncSetAttribute(attn_hmma, cudaFuncAttributeMaxDynamicSharedMemorySize, A2_SMEM);

    // 1: fused prep (x quant + 4 weight quants + rope table)
    prep_kernel<<<XB + 4*WB + 256, 256>>>(x, Wq, Wk, Wv, Wo);

    // 2: fused QKV projections (pure fp16; Q/K with in-epilogue RoPE)
    dim3 gq(DMODEL / 256, MROWS / 128, 3);   // (4, 64, 3)
    gemm_qkv<<<gq, GT, GEMM_SMEM>>>(bq, bk, bv);

    // 3: attention (fp16; writes fp16 g_O16)
    dim3 ag(TSEQ / 128, BSZ * NH);           // (16, 64)
    attn_hmma<<<ag, 256, A2_SMEM>>>(mk);

    // 4: output projection
    dim3 go(DMODEL / 256, MROWS / 128);      // (4, 64)
    gemm_out<<<go, GT, GEMM_SMEM>>>(bo, out);
}